// round 3
// baseline (speedup 1.0000x reference)
#include <cuda_runtime.h>
#include <cuda_bf16.h>
#include <cstdint>

// NT-Xent loss, N=4096, D=256, T=0.5.
// loss = mean_i ( lse_{j != i}(sim_ij) - sim_{i, i^4096} ),  sim = cos(z_i, z_j) / T
// Stable without max-tracking: sim in [-2, 2] => lse = 2 + log(sum exp(sim - 2)).

#define TWO_N 8192
#define HALF_N 4096
#define DD 256
#define ROWS_PER_BLK 32
#define CTILE 128
#define KC 16
#define NTHREADS 128
#define A_STRIDE 36    // 32 + pad, 16B-aligned rows
#define B_STRIDE 132   // 128 + pad, 16B-aligned rows

__device__ float g_zn[TWO_N * DD];     // normalized rows (8 MB, L2-resident)
__device__ float g_rowloss[TWO_N];

// ---------- packed f32x2 helpers (sm_103a FFMA2 path, PTX-only) ----------
__device__ __forceinline__ unsigned long long pack2(float lo, float hi) {
    unsigned long long r;
    asm("mov.b64 %0, {%1, %2};" : "=l"(r) : "f"(lo), "f"(hi));
    return r;
}
__device__ __forceinline__ void unpack2(unsigned long long v, float& lo, float& hi) {
    asm("mov.b64 {%0, %1}, %2;" : "=f"(lo), "=f"(hi) : "l"(v));
}
__device__ __forceinline__ void fma2(unsigned long long& acc,
                                     unsigned long long a, unsigned long long b) {
    asm("fma.rn.f32x2 %0, %1, %2, %0;" : "+l"(acc) : "l"(a), "l"(b));
}

// ---------- phase 1: row-normalize z = concat(z1, z2) ----------
__global__ void normalize_kernel(const float* __restrict__ z1,
                                 const float* __restrict__ z2) {
    int row = blockIdx.x;
    int t = threadIdx.x;
    const float* src = (row < HALF_N) ? (z1 + (size_t)row * DD)
                                      : (z2 + (size_t)(row - HALF_N) * DD);
    float v = src[t];
    float ss = v * v;
#pragma unroll
    for (int o = 16; o > 0; o >>= 1) ss += __shfl_xor_sync(0xffffffffu, ss, o);
    __shared__ float ws[8];
    __shared__ float s_inv;
    int w = t >> 5, lane = t & 31;
    if (lane == 0) ws[w] = ss;
    __syncthreads();
    if (t == 0) {
        float tot = 0.f;
#pragma unroll
        for (int j = 0; j < 8; j++) tot += ws[j];
        s_inv = 1.0f / fmaxf(sqrtf(tot), 1e-8f);
    }
    __syncthreads();
    g_zn[(size_t)row * DD + t] = v * s_inv;
}

// ---------- phase 2: streaming sim rows + online exp-sum ----------
// Grid: 256 blocks, each owns 32 rows and sweeps all 8192 columns in 128-col tiles.
// 128 threads, thread tile 4 rows x 8 cols (trow 0..7, tcol 0..15).
__global__ __launch_bounds__(NTHREADS) void ntxent_kernel() {
    __shared__ float A_s[KC][A_STRIDE];
    __shared__ float B_s[KC][B_STRIDE];

    int tid = threadIdx.x;
    int trow = tid >> 4;       // 0..7
    int tcol = tid & 15;       // 0..15
    int row0 = blockIdx.x * ROWS_PER_BLK;

    float psum[4] = {0.f, 0.f, 0.f, 0.f};
    float tv[4]   = {0.f, 0.f, 0.f, 0.f};

    int a_row = tid >> 2;                // 0..31
    int a_k4  = (tid & 3) << 2;          // 0,4,8,12

    for (int c0 = 0; c0 < TWO_N; c0 += CTILE) {
        unsigned long long acc[4][4];
#pragma unroll
        for (int i = 0; i < 4; i++)
#pragma unroll
            for (int j = 0; j < 4; j++) acc[i][j] = 0ull;

        for (int kc = 0; kc < DD; kc += KC) {
            __syncthreads();
            // A tile: 32 rows x 16 k (one float4 per thread)
            {
                const float4 av = *(const float4*)(&g_zn[(size_t)(row0 + a_row) * DD + kc + a_k4]);
                A_s[a_k4 + 0][a_row] = av.x;
                A_s[a_k4 + 1][a_row] = av.y;
                A_s[a_k4 + 2][a_row] = av.z;
                A_s[a_k4 + 3][a_row] = av.w;
            }
            // B tile: 128 cols x 16 k (four float4 per thread)
#pragma unroll
            for (int q = 0; q < 4; q++) {
                int fid = tid + q * NTHREADS;     // 0..511
                int br = fid >> 2;
                int bk = (fid & 3) << 2;
                const float4 bv = *(const float4*)(&g_zn[(size_t)(c0 + br) * DD + kc + bk]);
                B_s[bk + 0][br] = bv.x;
                B_s[bk + 1][br] = bv.y;
                B_s[bk + 2][br] = bv.z;
                B_s[bk + 3][br] = bv.w;
            }
            __syncthreads();

#pragma unroll
            for (int k = 0; k < KC; k++) {
                const float4 av = *(const float4*)(&A_s[k][trow << 2]);
                const float4 b0 = *(const float4*)(&B_s[k][tcol << 3]);
                const float4 b1 = *(const float4*)(&B_s[k][(tcol << 3) + 4]);
                unsigned long long bp0 = pack2(b0.x, b0.y);
                unsigned long long bp1 = pack2(b0.z, b0.w);
                unsigned long long bp2 = pack2(b1.x, b1.y);
                unsigned long long bp3 = pack2(b1.z, b1.w);
                unsigned long long a0 = pack2(av.x, av.x);
                unsigned long long a1 = pack2(av.y, av.y);
                unsigned long long a2 = pack2(av.z, av.z);
                unsigned long long a3 = pack2(av.w, av.w);
                fma2(acc[0][0], a0, bp0); fma2(acc[0][1], a0, bp1);
                fma2(acc[0][2], a0, bp2); fma2(acc[0][3], a0, bp3);
                fma2(acc[1][0], a1, bp0); fma2(acc[1][1], a1, bp1);
                fma2(acc[1][2], a1, bp2); fma2(acc[1][3], a1, bp3);
                fma2(acc[2][0], a2, bp0); fma2(acc[2][1], a2, bp1);
                fma2(acc[2][2], a2, bp2); fma2(acc[2][3], a2, bp3);
                fma2(acc[3][0], a3, bp0); fma2(acc[3][1], a3, bp1);
                fma2(acc[3][2], a3, bp2); fma2(acc[3][3], a3, bp3);
            }
        }

        // Epilogue (register-only): sim = 2*cos; exp(sim - 2); diag mask; target grab.
#pragma unroll
        for (int i = 0; i < 4; i++) {
            int R = row0 + (trow << 2) + i;
            int tgt = R ^ HALF_N;
            int cb = c0 + (tcol << 3);
#pragma unroll
            for (int jp = 0; jp < 4; jp++) {
                float lo, hi;
                unpack2(acc[i][jp], lo, hi);
                int Cl = cb + (jp << 1);
                int Ch = Cl + 1;
                float sl = lo + lo;   // * (1/T) = *2
                float sh = hi + hi;
                if (Cl != R) psum[i] += __expf(sl - 2.0f);
                if (Ch != R) psum[i] += __expf(sh - 2.0f);
                if (Cl == tgt) tv[i] = sl;
                if (Ch == tgt) tv[i] = sh;
            }
        }
    }

    // Reduce partials across the 16 tcol lanes (xor <= 8 stays within the 16-lane group).
#pragma unroll
    for (int i = 0; i < 4; i++) {
        float p = psum[i], t = tv[i];
#pragma unroll
        for (int o = 8; o > 0; o >>= 1) {
            p += __shfl_xor_sync(0xffffffffu, p, o);
            t += __shfl_xor_sync(0xffffffffu, t, o);
        }
        if (tcol == 0) {
            int R = row0 + (trow << 2) + i;
            g_rowloss[R] = (2.0f + logf(p)) - t;
        }
    }
}

// ---------- phase 3: mean over rows ----------
__global__ void reduce_kernel(float* __restrict__ out) {
    int t = threadIdx.x;
    float s = 0.f;
    for (int i = t; i < TWO_N; i += 256) s += g_rowloss[i];
#pragma unroll
    for (int o = 16; o > 0; o >>= 1) s += __shfl_xor_sync(0xffffffffu, s, o);
    __shared__ float ws[8];
    if ((t & 31) == 0) ws[t >> 5] = s;
    __syncthreads();
    if (t == 0) {
        float tot = 0.f;
#pragma unroll
        for (int j = 0; j < 8; j++) tot += ws[j];
        out[0] = tot * (1.0f / (float)TWO_N);
    }
}

extern "C" void kernel_launch(void* const* d_in, const int* in_sizes, int n_in,
                              void* d_out, int out_size) {
    const float* z1 = (const float*)d_in[0];
    const float* z2 = (const float*)d_in[1];
    float* out = (float*)d_out;
    (void)in_sizes; (void)n_in; (void)out_size;

    normalize_kernel<<<TWO_N, DD>>>(z1, z2);
    ntxent_kernel<<<TWO_N / ROWS_PER_BLK, NTHREADS>>>();
    reduce_kernel<<<1, 256>>>(out);
}

// round 4
// speedup vs baseline: 6.9612x; 6.9612x over previous
#include <cuda_runtime.h>
#include <cuda_bf16.h>
#include <cstdint>

// NT-Xent loss, N=4096, D=256, T=0.5 — bf16 tensor-core (HMMA) version.
// loss = mean_i ( lse_{j != i}(sim_ij) - sim_{i, i^4096} ),  sim = cos(z_i,z_j)/T.
// cos in [-1,1] => sim in [-2,2] => lse = 2 + log(sum exp(sim-2)) is stable, no max pass.

#define TWO_N 8192
#define HALF_N 4096
#define DD 256
#define BM 64
#define BN 128
#define SB 264            // padded smem row stride in bf16 elems (528 B => 4-bank shift/row, LDSM conflict-free)
#define SBB 528           // bytes
#define NTHREADS 256

__device__ __nv_bfloat16 g_znb[TWO_N * DD];  // normalized rows, bf16 (4 MB, L2-resident)
__device__ float g_rowloss[TWO_N];

#define A_ELEMS (BM * SB)                        // 16896
#define B_ELEMS (BN * SB)                        // 33792
#define SMEM_BYTES ((A_ELEMS + 2 * B_ELEMS) * 2) // 168960 B

// ---------------- PTX helpers ----------------
__device__ __forceinline__ void cp16(uint32_t dst, const void* src) {
    asm volatile("cp.async.cg.shared.global [%0], [%1], 16;" :: "r"(dst), "l"(src));
}
__device__ __forceinline__ void cp_commit() { asm volatile("cp.async.commit_group;"); }
template <int N> __device__ __forceinline__ void cp_wait() {
    asm volatile("cp.async.wait_group %0;" :: "n"(N));
}
__device__ __forceinline__ void ldsm4(uint32_t& x0, uint32_t& x1, uint32_t& x2, uint32_t& x3,
                                      uint32_t addr) {
    asm volatile("ldmatrix.sync.aligned.m8n8.x4.shared.b16 {%0,%1,%2,%3}, [%4];"
                 : "=r"(x0), "=r"(x1), "=r"(x2), "=r"(x3) : "r"(addr));
}
__device__ __forceinline__ void mma16816(float* c, const uint32_t* a, uint32_t b0, uint32_t b1) {
    asm volatile("mma.sync.aligned.m16n8k16.row.col.f32.bf16.bf16.f32 "
                 "{%0,%1,%2,%3}, {%4,%5,%6,%7}, {%8,%9}, {%0,%1,%2,%3};"
                 : "+f"(c[0]), "+f"(c[1]), "+f"(c[2]), "+f"(c[3])
                 : "r"(a[0]), "r"(a[1]), "r"(a[2]), "r"(a[3]), "r"(b0), "r"(b1));
}

// ---------------- phase 1: normalize, fp32 -> bf16 ----------------
__global__ void normalize_kernel(const float* __restrict__ z1,
                                 const float* __restrict__ z2) {
    int row = blockIdx.x;
    int t = threadIdx.x;
    const float* src = (row < HALF_N) ? (z1 + (size_t)row * DD)
                                      : (z2 + (size_t)(row - HALF_N) * DD);
    float v = src[t];
    float ss = v * v;
#pragma unroll
    for (int o = 16; o > 0; o >>= 1) ss += __shfl_xor_sync(0xffffffffu, ss, o);
    __shared__ float ws[8];
    __shared__ float s_inv;
    int w = t >> 5, lane = t & 31;
    if (lane == 0) ws[w] = ss;
    __syncthreads();
    if (t == 0) {
        float tot = 0.f;
#pragma unroll
        for (int j = 0; j < 8; j++) tot += ws[j];
        s_inv = 1.0f / fmaxf(sqrtf(tot), 1e-8f);
    }
    __syncthreads();
    g_znb[(size_t)row * DD + t] = __float2bfloat16(v * s_inv);
}

// ---------------- phase 2: HMMA sim sweep + online exp-sum ----------------
// 128 blocks x 256 thr. Block owns 64 rows (A resident in smem), sweeps 8192 cols
// in 128-col tiles (double-buffered cp.async). Warp tile m32 x n32.
__global__ __launch_bounds__(NTHREADS, 1) void ntxent_mma_kernel() {
    extern __shared__ __align__(16) char smem[];
    __nv_bfloat16* As = (__nv_bfloat16*)smem;

    const int tid = threadIdx.x;
    const int lane = tid & 31, wid = tid >> 5;
    const int warp_m = wid & 1;    // 0..1 -> which 32-row half
    const int warp_n = wid >> 1;   // 0..3 -> which 32-col slice
    const int row0 = blockIdx.x * BM;

    const uint32_t As_u = (uint32_t)__cvta_generic_to_shared(As);
    const uint32_t Bs_u0 = As_u + A_ELEMS * 2;
    const uint32_t Bs_u1 = Bs_u0 + B_ELEMS * 2;

    // --- prologue loads: A band (once) + B tile 0 ---
#pragma unroll
    for (int q = 0; q < 8; q++) {          // 64*256 bf16 = 2048 x 16B chunks
        int ch = tid + q * NTHREADS;
        int row = ch >> 5, off = ch & 31;
        cp16(As_u + row * SBB + off * 16, g_znb + (size_t)(row0 + row) * DD + off * 8);
    }
#pragma unroll
    for (int q = 0; q < 16; q++) {         // 128*256 bf16 = 4096 x 16B chunks
        int ch = tid + q * NTHREADS;
        int row = ch >> 5, off = ch & 31;
        cp16(Bs_u0 + row * SBB + off * 16, g_znb + (size_t)row * DD + off * 8);
    }
    cp_commit();

    // --- ldmatrix per-lane addressing ---
    const int g = lane >> 3, rr = lane & 7;
    const uint32_t a_off0 = (uint32_t)((warp_m * 32 + (lane & 15)) * SBB + (lane >> 4) * 16);
    const uint32_t a_off1 = a_off0 + 16 * SBB;
    const uint32_t b_off0 = (uint32_t)((warp_n * 32 + (g >> 1) * 8 + rr) * SBB + (g & 1) * 16);
    const uint32_t b_off1 = b_off0 + 16 * SBB;

    const int gid = lane >> 2, qd = lane & 3;

    float p[2][2]  = {{0.f, 0.f}, {0.f, 0.f}};
    float tv[2][2] = {{0.f, 0.f}, {0.f, 0.f}};

    for (int it = 0; it < TWO_N / BN; it++) {
        const int c0 = it * BN;
        const int cn = (c0 + BN) & (TWO_N - 1);
        const uint32_t Bu_cur = (it & 1) ? Bs_u1 : Bs_u0;
        const uint32_t Bu_nxt = (it & 1) ? Bs_u0 : Bs_u1;

        __syncthreads();                    // prev compute done before overwriting nxt buffer
#pragma unroll
        for (int q = 0; q < 16; q++) {      // prefetch next B tile
            int ch = tid + q * NTHREADS;
            int row = ch >> 5, off = ch & 31;
            cp16(Bu_nxt + row * SBB + off * 16, g_znb + (size_t)(cn + row) * DD + off * 8);
        }
        cp_commit();
        cp_wait<1>();                       // current tile (and A on it=0) landed
        __syncthreads();

        float acc[2][4][4];
#pragma unroll
        for (int mi = 0; mi < 2; mi++)
#pragma unroll
            for (int j = 0; j < 4; j++)
#pragma unroll
                for (int r4 = 0; r4 < 4; r4++) acc[mi][j][r4] = 0.f;

#pragma unroll
        for (int kk = 0; kk < DD / 16; kk++) {
            uint32_t a0[4], a1[4], bb0[4], bb1[4];
            ldsm4(a0[0], a0[1], a0[2], a0[3], As_u + a_off0 + kk * 32);
            ldsm4(a1[0], a1[1], a1[2], a1[3], As_u + a_off1 + kk * 32);
            ldsm4(bb0[0], bb0[1], bb0[2], bb0[3], Bu_cur + b_off0 + kk * 32);
            ldsm4(bb1[0], bb1[1], bb1[2], bb1[3], Bu_cur + b_off1 + kk * 32);
            mma16816(acc[0][0], a0, bb0[0], bb0[1]);
            mma16816(acc[0][1], a0, bb0[2], bb0[3]);
            mma16816(acc[0][2], a0, bb1[0], bb1[1]);
            mma16816(acc[0][3], a0, bb1[2], bb1[3]);
            mma16816(acc[1][0], a1, bb0[0], bb0[1]);
            mma16816(acc[1][1], a1, bb0[2], bb0[3]);
            mma16816(acc[1][2], a1, bb1[0], bb1[1]);
            mma16816(acc[1][3], a1, bb1[2], bb1[3]);
        }

        // --- register-only epilogue: sim = 2*cos; accumulate exp(sim-2), grab target ---
#pragma unroll
        for (int mi = 0; mi < 2; mi++) {
            const int R1 = row0 + warp_m * 32 + mi * 16 + gid;
            const int R2 = R1 + 8;
            const int T1 = R1 ^ HALF_N, T2 = R2 ^ HALF_N;
#pragma unroll
            for (int j = 0; j < 4; j++) {
                const int C0 = c0 + warp_n * 32 + j * 8 + qd * 2;
                const int C1 = C0 + 1;
                const float s00 = acc[mi][j][0] * 2.f, s01 = acc[mi][j][1] * 2.f;
                const float s10 = acc[mi][j][2] * 2.f, s11 = acc[mi][j][3] * 2.f;
                if (C0 != R1) p[mi][0] += __expf(s00 - 2.f);
                if (C1 != R1) p[mi][0] += __expf(s01 - 2.f);
                if (C0 != R2) p[mi][1] += __expf(s10 - 2.f);
                if (C1 != R2) p[mi][1] += __expf(s11 - 2.f);
                tv[mi][0] += (C0 == T1) ? s00 : 0.f;
                tv[mi][0] += (C1 == T1) ? s01 : 0.f;
                tv[mi][1] += (C0 == T2) ? s10 : 0.f;
                tv[mi][1] += (C1 == T2) ? s11 : 0.f;
            }
        }
    }

    cp_wait<0>();   // drain the dangling last prefetch before smem reuse / exit

    // --- reduce across the 4 quad lanes, then across the 4 warp_n warps via smem ---
#pragma unroll
    for (int mi = 0; mi < 2; mi++)
#pragma unroll
        for (int h = 0; h < 2; h++) {
            float pp = p[mi][h], tt = tv[mi][h];
            pp += __shfl_xor_sync(0xffffffffu, pp, 1);
            pp += __shfl_xor_sync(0xffffffffu, pp, 2);
            tt += __shfl_xor_sync(0xffffffffu, tt, 1);
            tt += __shfl_xor_sync(0xffffffffu, tt, 2);
            p[mi][h] = pp; tv[mi][h] = tt;
        }

    __syncthreads();
    float* redp = (float*)smem;        // [64][4]
    float* redt = redp + BM * 4;
    if (qd == 0) {
#pragma unroll
        for (int mi = 0; mi < 2; mi++)
#pragma unroll
            for (int h = 0; h < 2; h++) {
                int rl = warp_m * 32 + mi * 16 + h * 8 + gid;
                redp[rl * 4 + warp_n] = p[mi][h];
                redt[rl * 4 + warp_n] = tv[mi][h];
            }
    }
    __syncthreads();
    if (tid < BM) {
        float pp = redp[tid * 4] + redp[tid * 4 + 1] + redp[tid * 4 + 2] + redp[tid * 4 + 3];
        float tt = redt[tid * 4] + redt[tid * 4 + 1] + redt[tid * 4 + 2] + redt[tid * 4 + 3];
        g_rowloss[row0 + tid] = 2.0f + logf(pp) - tt;
    }
}

// ---------------- phase 3: mean over rows ----------------
__global__ void reduce_kernel(float* __restrict__ out) {
    int t = threadIdx.x;
    float s = 0.f;
    for (int i = t; i < TWO_N; i += 256) s += g_rowloss[i];
#pragma unroll
    for (int o = 16; o > 0; o >>= 1) s += __shfl_xor_sync(0xffffffffu, s, o);
    __shared__ float ws[8];
    if ((t & 31) == 0) ws[t >> 5] = s;
    __syncthreads();
    if (t == 0) {
        float tot = 0.f;
#pragma unroll
        for (int j = 0; j < 8; j++) tot += ws[j];
        out[0] = tot * (1.0f / (float)TWO_N);
    }
}

extern "C" void kernel_launch(void* const* d_in, const int* in_sizes, int n_in,
                              void* d_out, int out_size) {
    const float* z1 = (const float*)d_in[0];
    const float* z2 = (const float*)d_in[1];
    float* out = (float*)d_out;
    (void)in_sizes; (void)n_in; (void)out_size;

    cudaFuncSetAttribute(ntxent_mma_kernel,
                         cudaFuncAttributeMaxDynamicSharedMemorySize, SMEM_BYTES);

    normalize_kernel<<<TWO_N, DD>>>(z1, z2);
    ntxent_mma_kernel<<<TWO_N / BM, NTHREADS, SMEM_BYTES>>>();
    reduce_kernel<<<1, 256>>>(out);
}

// round 11
// speedup vs baseline: 12.6510x; 1.8174x over previous
#include <cuda_runtime.h>
#include <cuda_bf16.h>
#include <cstdint>

// NT-Xent loss, N=4096, D=256, T=0.5 — bf16 mma.sync HMMA, 16-warp CTAs.
// sim = cos/T in [-2,2] => lse = 2 + log(sum exp(sim-2)) : stable, no max pass.
// Grid 128 = 64 row-bands(128 rows) x 2 column halves(4096 cols).
// Per CTA: A band [128x256] smem-resident; 32 B tiles [128x256] double-buffered
// cp.async; warp grid 4x4, warp tile m32 x n32; register-only exp epilogue.

#define TWO_N 8192
#define HALF_N 4096
#define DD 256
#define BM 128
#define BN 128
#define NT 32              // tiles per CTA (4096 / BN)
#define SB 264             // padded smem row stride (bf16 elems); 528 B rows
#define SBB 528
#define NTHREADS 512

__device__ __nv_bfloat16 g_znb[TWO_N * DD];   // normalized rows bf16 (4 MB, L2-resident)
__device__ float g_p[2 * TWO_N];              // per-half exp-sum partials
__device__ float g_t[2 * TWO_N];              // per-half target partials

#define A_ELEMS (BM * SB)
#define B_ELEMS (BN * SB)
#define SMEM_BYTES ((A_ELEMS + 2 * B_ELEMS) * 2)   // 202752 B

// ---------------- PTX helpers ----------------
__device__ __forceinline__ void cp16(uint32_t dst, const void* src) {
    asm volatile("cp.async.cg.shared.global [%0], [%1], 16;" :: "r"(dst), "l"(src));
}
__device__ __forceinline__ void cp_commit() { asm volatile("cp.async.commit_group;"); }
template <int N> __device__ __forceinline__ void cp_wait() {
    asm volatile("cp.async.wait_group %0;" :: "n"(N));
}
__device__ __forceinline__ void ldsm4(uint32_t& x0, uint32_t& x1, uint32_t& x2, uint32_t& x3,
                                      uint32_t addr) {
    asm volatile("ldmatrix.sync.aligned.m8n8.x4.shared.b16 {%0,%1,%2,%3}, [%4];"
                 : "=r"(x0), "=r"(x1), "=r"(x2), "=r"(x3) : "r"(addr));
}
__device__ __forceinline__ void mma16816(float* c, const uint32_t* a, uint32_t b0, uint32_t b1) {
    asm volatile("mma.sync.aligned.m16n8k16.row.col.f32.bf16.bf16.f32 "
                 "{%0,%1,%2,%3}, {%4,%5,%6,%7}, {%8,%9}, {%0,%1,%2,%3};"
                 : "+f"(c[0]), "+f"(c[1]), "+f"(c[2]), "+f"(c[3])
                 : "r"(a[0]), "r"(a[1]), "r"(a[2]), "r"(a[3]), "r"(b0), "r"(b1));
}

// ---------------- phase 1: normalize fp32 -> bf16 (warp per row) ----------------
__global__ void normalize_kernel(const float* __restrict__ z1,
                                 const float* __restrict__ z2) {
    int w = threadIdx.x >> 5, lane = threadIdx.x & 31;
    int row = blockIdx.x * 8 + w;
    const float* src = (row < HALF_N) ? (z1 + (size_t)row * DD)
                                      : (z2 + (size_t)(row - HALF_N) * DD);
    float4 f0 = *(const float4*)(src + lane * 8);
    float4 f1 = *(const float4*)(src + lane * 8 + 4);
    float ss = f0.x * f0.x + f0.y * f0.y + f0.z * f0.z + f0.w * f0.w
             + f1.x * f1.x + f1.y * f1.y + f1.z * f1.z + f1.w * f1.w;
#pragma unroll
    for (int o = 16; o > 0; o >>= 1) ss += __shfl_xor_sync(0xffffffffu, ss, o);
    float inv = 1.0f / fmaxf(sqrtf(ss), 1e-8f);

    __nv_bfloat16 ob[8];
    ob[0] = __float2bfloat16(f0.x * inv); ob[1] = __float2bfloat16(f0.y * inv);
    ob[2] = __float2bfloat16(f0.z * inv); ob[3] = __float2bfloat16(f0.w * inv);
    ob[4] = __float2bfloat16(f1.x * inv); ob[5] = __float2bfloat16(f1.y * inv);
    ob[6] = __float2bfloat16(f1.z * inv); ob[7] = __float2bfloat16(f1.w * inv);
    *(uint4*)(g_znb + (size_t)row * DD + lane * 8) = *(const uint4*)ob;
}

// ---------------- phase 2: HMMA sweep + online exp-sum ----------------
__global__ __launch_bounds__(NTHREADS, 1) void ntxent_mma_kernel() {
    extern __shared__ __align__(16) char smem[];
    __nv_bfloat16* As = (__nv_bfloat16*)smem;

    const int tid = threadIdx.x;
    const int lane = tid & 31, wid = tid >> 5;
    const int warp_m = wid & 3;    // 0..3 -> 32-row slice
    const int warp_n = wid >> 2;   // 0..3 -> 32-col slice
    const int band = blockIdx.x >> 1;
    const int ch = blockIdx.x & 1;
    const int row0 = band * BM;
    const int colbase = ch * (NT * BN);   // 0 or 4096

    const uint32_t As_u = (uint32_t)__cvta_generic_to_shared(As);
    const uint32_t Bs_u0 = As_u + A_ELEMS * 2;
    const uint32_t Bs_u1 = Bs_u0 + B_ELEMS * 2;

    // --- prologue: A band + B tile 0 (one group) ---
#pragma unroll
    for (int q = 0; q < 8; q++) {          // 128*256 bf16 = 4096 x 16B chunks
        int c = tid + q * NTHREADS;
        int row = c >> 5, off = c & 31;
        cp16(As_u + row * SBB + off * 16, g_znb + (size_t)(row0 + row) * DD + off * 8);
        cp16(Bs_u0 + row * SBB + off * 16, g_znb + (size_t)(colbase + row) * DD + off * 8);
    }
    cp_commit();

    // --- ldmatrix per-lane addressing (verified layout from R4) ---
    const int g = lane >> 3, rr = lane & 7;
    const uint32_t a_off0 = (uint32_t)((warp_m * 32 + (lane & 15)) * SBB + (lane >> 4) * 16);
    const uint32_t a_off1 = a_off0 + 16 * SBB;
    const uint32_t b_off0 = (uint32_t)((warp_n * 32 + (g >> 1) * 8 + rr) * SBB + (g & 1) * 16);
    const uint32_t b_off1 = b_off0 + 16 * SBB;

    const int gid = lane >> 2, qd = lane & 3;

    float p[2][2]  = {{0.f, 0.f}, {0.f, 0.f}};
    float tv[2][2] = {{0.f, 0.f}, {0.f, 0.f}};

    for (int it = 0; it < NT; it++) {
        const int c0 = colbase + it * BN;
        const int cn = colbase + ((it + 1) & (NT - 1)) * BN;   // wrap on last iter (discarded)
        const uint32_t Bu_cur = (it & 1) ? Bs_u1 : Bs_u0;
        const uint32_t Bu_nxt = (it & 1) ? Bs_u0 : Bs_u1;

        __syncthreads();                    // prev tile's compute done before overwriting nxt
#pragma unroll
        for (int q = 0; q < 8; q++) {       // prefetch next B tile
            int c = tid + q * NTHREADS;
            int row = c >> 5, off = c & 31;
            cp16(Bu_nxt + row * SBB + off * 16, g_znb + (size_t)(cn + row) * DD + off * 8);
        }
        cp_commit();
        cp_wait<1>();                       // current tile (and A on it=0) landed
        __syncthreads();

        float acc[2][4][4];
#pragma unroll
        for (int mi = 0; mi < 2; mi++)
#pragma unroll
            for (int j = 0; j < 4; j++)
#pragma unroll
                for (int r4 = 0; r4 < 4; r4++) acc[mi][j][r4] = 0.f;

#pragma unroll
        for (int kk = 0; kk < DD / 16; kk++) {
            uint32_t a0[4], a1[4], bb0[4], bb1[4];
            ldsm4(a0[0], a0[1], a0[2], a0[3], As_u + a_off0 + kk * 32);
            ldsm4(a1[0], a1[1], a1[2], a1[3], As_u + a_off1 + kk * 32);
            ldsm4(bb0[0], bb0[1], bb0[2], bb0[3], Bu_cur + b_off0 + kk * 32);
            ldsm4(bb1[0], bb1[1], bb1[2], bb1[3], Bu_cur + b_off1 + kk * 32);
            mma16816(acc[0][0], a0, bb0[0], bb0[1]);
            mma16816(acc[0][1], a0, bb0[2], bb0[3]);
            mma16816(acc[0][2], a0, bb1[0], bb1[1]);
            mma16816(acc[0][3], a0, bb1[2], bb1[3]);
            mma16816(acc[1][0], a1, bb0[0], bb0[1]);
            mma16816(acc[1][1], a1, bb0[2], bb0[3]);
            mma16816(acc[1][2], a1, bb1[0], bb1[1]);
            mma16816(acc[1][3], a1, bb1[2], bb1[3]);
        }

        // --- register-only epilogue ---
#pragma unroll
        for (int mi = 0; mi < 2; mi++) {
            const int R1 = row0 + warp_m * 32 + mi * 16 + gid;
            const int R2 = R1 + 8;
            const int T1 = R1 ^ HALF_N, T2 = R2 ^ HALF_N;
#pragma unroll
            for (int j = 0; j < 4; j++) {
                const int C0 = c0 + warp_n * 32 + j * 8 + qd * 2;
                const int C1 = C0 + 1;
                const float s00 = acc[mi][j][0] * 2.f, s01 = acc[mi][j][1] * 2.f;
                const float s10 = acc[mi][j][2] * 2.f, s11 = acc[mi][j][3] * 2.f;
                if (C0 != R1) p[mi][0] += __expf(s00 - 2.f);
                if (C1 != R1) p[mi][0] += __expf(s01 - 2.f);
                if (C0 != R2) p[mi][1] += __expf(s10 - 2.f);
                if (C1 != R2) p[mi][1] += __expf(s11 - 2.f);
                tv[mi][0] += (C0 == T1) ? s00 : 0.f;
                tv[mi][0] += (C1 == T1) ? s01 : 0.f;
                tv[mi][1] += (C0 == T2) ? s10 : 0.f;
                tv[mi][1] += (C1 == T2) ? s11 : 0.f;
            }
        }
    }

    cp_wait<0>();     // drain the dangling wrapped prefetch

    // --- reduce quad lanes, then 4 warp_n warps via smem ---
#pragma unroll
    for (int mi = 0; mi < 2; mi++)
#pragma unroll
        for (int h = 0; h < 2; h++) {
            float pp = p[mi][h], tt = tv[mi][h];
            pp += __shfl_xor_sync(0xffffffffu, pp, 1);
            pp += __shfl_xor_sync(0xffffffffu, pp, 2);
            tt += __shfl_xor_sync(0xffffffffu, tt, 1);
            tt += __shfl_xor_sync(0xffffffffu, tt, 2);
            p[mi][h] = pp; tv[mi][h] = tt;
        }

    __syncthreads();
    float* redp = (float*)smem;            // [128][4]
    float* redt = redp + BM * 4;
    if (qd == 0) {
#pragma unroll
        for (int mi = 0; mi < 2; mi++)
#pragma unroll
            for (int h = 0; h < 2; h++) {
                int rl = warp_m * 32 + mi * 16 + h * 8 + gid;
                redp[rl * 4 + warp_n] = p[mi][h];
                redt[rl * 4 + warp_n] = tv[mi][h];
            }
    }
    __syncthreads();
    if (tid < BM) {
        float pp = redp[tid * 4] + redp[tid * 4 + 1] + redp[tid * 4 + 2] + redp[tid * 4 + 3];
        float tt = redt[tid * 4] + redt[tid * 4 + 1] + redt[tid * 4 + 2] + redt[tid * 4 + 3];
        g_p[ch * TWO_N + row0 + tid] = pp;
        g_t[ch * TWO_N + row0 + tid] = tt;
    }
}

// ---------------- phase 3: combine halves, log, mean ----------------
__global__ void reduce_kernel(float* __restrict__ out) {
    int t = threadIdx.x;
    float s = 0.f;
    for (int i = t; i < TWO_N; i += 256) {
        float pp = g_p[i] + g_p[TWO_N + i];
        float tt = g_t[i] + g_t[TWO_N + i];
        s += 2.0f + logf(pp) - tt;
    }
#pragma unroll
    for (int o = 16; o > 0; o >>= 1) s += __shfl_xor_sync(0xffffffffu, s, o);
    __shared__ float ws[8];
    if ((t & 31) == 0) ws[t >> 5] = s;
    __syncthreads();
    if (t == 0) {
        float tot = 0.f;
#pragma unroll
        for (int j = 0; j < 8; j++) tot += ws[j];
        out[0] = tot * (1.0f / (float)TWO_N);
    }
}

extern "C" void kernel_launch(void* const* d_in, const int* in_sizes, int n_in,
                              void* d_out, int out_size) {
    const float* z1 = (const float*)d_in[0];
    const float* z2 = (const float*)d_in[1];
    float* out = (float*)d_out;
    (void)in_sizes; (void)n_in; (void)out_size;

    cudaFuncSetAttribute(ntxent_mma_kernel,
                         cudaFuncAttributeMaxDynamicSharedMemorySize, SMEM_BYTES);

    normalize_kernel<<<TWO_N / 8, 256>>>(z1, z2);
    ntxent_mma_kernel<<<(TWO_N / BM) * 2, NTHREADS, SMEM_BYTES>>>();
    reduce_kernel<<<1, 256>>>(out);
}